// round 15
// baseline (speedup 1.0000x reference)
#include <cuda_runtime.h>

typedef unsigned long long u64;

// ---------------- problem constants ----------------
#define HW      4096
#define OUTW    4090          // valid output size (HW - 6)
#define TPB     128
#define KCOLS   8             // output columns per thread
#define RROWS   28            // output rows per block strip
#define NTX     4             // 4 * 128 * 8 = 4096 columns
#define NSTRIPS 148           // 148 * 28 = 4144 >= 4090 ; 4*148 = 592 blocks = 4/SM
#define NBLOCKS (NTX * NSTRIPS)

#define SSIM_C1 0.0004f            // (0.01*2)^2
#define SSIM_C2 0.0036f            // (0.03*2)^2
#define INV49   (1.0f/49.0f)
#define H1CONST (0.5f*INV49*INV49) // A1 = H1*(wP^2 - wM^2) + C1
#define G1CONST (1.0f/96.0f)       // A2 = G1*(a2 - b2) + C2  (covnorm/2/49 folded)

__device__ float g_partials[NBLOCKS];
__device__ int   g_count = 0;

// ---------------- packed f32x2 helpers (ptxas never emits FFMA2 from C++) ----
__device__ __forceinline__ u64 f2add(u64 a, u64 b){ u64 r; asm("add.rn.f32x2 %0,%1,%2;" : "=l"(r) : "l"(a), "l"(b)); return r; }
__device__ __forceinline__ u64 f2mul(u64 a, u64 b){ u64 r; asm("mul.rn.f32x2 %0,%1,%2;" : "=l"(r) : "l"(a), "l"(b)); return r; }
__device__ __forceinline__ u64 f2fma(u64 a, u64 b, u64 c){ u64 r; asm("fma.rn.f32x2 %0,%1,%2,%3;" : "=l"(r) : "l"(a), "l"(b), "l"(c)); return r; }
__device__ __forceinline__ u64 pack2(float lo, float hi){ u64 r; asm("mov.b64 %0,{%1,%2};" : "=l"(r) : "f"(lo), "f"(hi)); return r; }
__device__ __forceinline__ float2 unpack2(u64 v){ float2 r; asm("mov.b64 {%0,%1},%2;" : "=f"(r.x), "=f"(r.y) : "l"(v)); return r; }
__device__ __forceinline__ u64 bcast2(float f){ return pack2(f, f); }

// From 7 column-pair sums (14 scalar columns), build 4 packed pixel-pair
// 7-wide horizontal window sums: W[p] = { w(2p), w(2p+1) }.
__device__ __forceinline__ void windows(const u64* s, u64* W){
    float v[14];
#pragma unroll
    for (int j = 0; j < 7; ++j){ float2 t = unpack2(s[j]); v[2*j] = t.x; v[2*j+1] = t.y; }
    float w = v[0]+v[1]+v[2]+v[3]+v[4]+v[5]+v[6];
#pragma unroll
    for (int p = 0; p < 4; ++p){
        float w0 = w;
        w = w - v[2*p] + v[2*p+7];
        float w1 = w;
        if (p < 3) w = w - v[2*p+1] + v[2*p+8];
        W[p] = pack2(w0, w1);
    }
}

__global__ __launch_bounds__(TPB, 3)
void ssim_main(const float* __restrict__ O, const float* __restrict__ T,
               float* __restrict__ out) {
    const int base = blockIdx.x * (TPB * KCOLS) + threadIdx.x * KCOLS;
    const int y0   = blockIdx.y * RROWS;
    const int yend = min(y0 + RROWS, OUTW);
    const int nvalid = min(KCOLS, OUTW - base);   // >= 2 for every thread

    float acc = 0.f;

    if (y0 < yend) {
        // 7 column-pair offsets (u64 index), clamped for the single tail thread.
        // Clamped pairs only feed invalid output columns (nvalid guards them).
        int off2[7];
#pragma unroll
        for (int j = 0; j < 7; ++j) off2[j] = min(base + 2*j, HW - 2) >> 1;

        const u64 NEG1 = bcast2(-1.0f);
        const u64 NI49 = bcast2(-INV49);
        const u64 H1v  = bcast2(H1CONST);
        const u64 G1v  = bcast2(G1CONST);
        const u64 C1v  = bcast2(SSIM_C1);
        const u64 C2v  = bcast2(SSIM_C2);

        // Packed vertical column sums over 7 rows: P=O+T, M=O-T, P^2, M^2.
        u64 sP[7], sM[7], sPP[7], sMM[7];
#pragma unroll
        for (int j = 0; j < 7; ++j){ sP[j]=0; sM[j]=0; sPP[j]=0; sMM[j]=0; }

        // ---- init: rows y0 .. y0+6 ----
        for (int r = 0; r < 7; ++r){
            const u64* oR = reinterpret_cast<const u64*>(O + (y0 + r) * HW);
            const u64* tR = reinterpret_cast<const u64*>(T + (y0 + r) * HW);
#pragma unroll
            for (int j = 0; j < 7; ++j){
                u64 o = oR[off2[j]], t = tR[off2[j]];
                u64 P = f2add(o, t);
                u64 M = f2fma(t, NEG1, o);
                sP[j]  = f2add(sP[j], P);
                sM[j]  = f2add(sM[j], M);
                sPP[j] = f2fma(P, P, sPP[j]);
                sMM[j] = f2fma(M, M, sMM[j]);
            }
        }

        for (int y = y0; y < yend; ++y){
            // ---- horizontal windows (packed pixel pairs) ----
            u64 WP[4], WM[4], WPP[4], WMM[4];
            windows(sP,  WP);  windows(sM,  WM);
            windows(sPP, WPP); windows(sMM, WMM);

            // ---- packed SSIM epilogue, 2 pixels per f32x2 op ----
#pragma unroll
            for (int p = 0; p < 4; ++p){
                u64 PS2 = f2mul(WP[p], WP[p]);          // wP^2 (unscaled)
                u64 MS2 = f2mul(WM[p], WM[p]);
                u64 a2  = f2fma(PS2, NI49, WPP[p]);     // wPP - wP^2/49
                u64 b2  = f2fma(MS2, NI49, WMM[p]);
                u64 df1 = f2fma(MS2, NEG1, PS2);        // PS2 - MS2
                u64 sm1 = f2add(PS2, MS2);
                u64 A1  = f2fma(df1, H1v, C1v);         // 2*ux*uy + C1
                u64 B1  = f2fma(sm1, H1v, C1v);         // ux^2+uy^2 + C1
                u64 df2 = f2fma(b2, NEG1, a2);
                u64 sm2 = f2add(a2, b2);
                u64 A2  = f2fma(df2, G1v, C2v);         // 2*vxy + C2
                u64 B2  = f2fma(sm2, G1v, C2v);         // vx+vy + C2
                float2 num = unpack2(f2mul(A1, A2));
                float2 den = unpack2(f2mul(B1, B2));
                if (2*p     < nvalid) acc += __fdividef(num.x, den.x);
                if (2*p + 1 < nvalid) acc += __fdividef(num.y, den.y);
            }

            // ---- packed vertical slide: add row y+7, remove row y ----
            if (y + 1 < yend){
                const u64* oN = reinterpret_cast<const u64*>(O + (y + 7) * HW);
                const u64* tN = reinterpret_cast<const u64*>(T + (y + 7) * HW);
                const u64* oO = reinterpret_cast<const u64*>(O + y * HW);   // L1/L2-hot
                const u64* tO = reinterpret_cast<const u64*>(T + y * HW);
#pragma unroll
                for (int j = 0; j < 7; ++j){
                    u64 on = oN[off2[j]], tn = tN[off2[j]];
                    u64 oo = oO[off2[j]], to = tO[off2[j]];
                    u64 Pn = f2add(on, tn);
                    u64 Mn = f2fma(tn, NEG1, on);
                    u64 Po = f2add(oo, to);
                    u64 Mo = f2fma(to, NEG1, oo);
                    u64 dP = f2fma(Po, NEG1, Pn);
                    u64 dM = f2fma(Mo, NEG1, Mn);
                    sP[j] = f2add(sP[j], dP);
                    sM[j] = f2add(sM[j], dM);
                    u64 tP = f2add(Pn, Po);
                    u64 tM = f2add(Mn, Mo);
                    sPP[j] = f2fma(dP, tP, sPP[j]);     // Pn^2 - Po^2
                    sMM[j] = f2fma(dM, tM, sMM[j]);
                }
            }
        }
    }

    // ---- deterministic block reduction ----
#pragma unroll
    for (int o = 16; o > 0; o >>= 1)
        acc += __shfl_down_sync(0xffffffffu, acc, o);

    __shared__ float warpsum[TPB / 32];
    __shared__ bool  amLast;
    if ((threadIdx.x & 31) == 0) warpsum[threadIdx.x >> 5] = acc;
    __syncthreads();
    if (threadIdx.x == 0){
        float s = warpsum[0] + warpsum[1] + warpsum[2] + warpsum[3];
        g_partials[blockIdx.y * gridDim.x + blockIdx.x] = s;
        __threadfence();
        int prev = atomicAdd(&g_count, 1);
        amLast = (prev == NBLOCKS - 1);
    }
    __syncthreads();

    // ---- fused finalize: last block reduces all partials (fixed order) ----
    if (amLast){
        __shared__ double sh[TPB];
        double d = 0.0;
        for (int i = threadIdx.x; i < NBLOCKS; i += TPB)
            d += (double)g_partials[i];
        sh[threadIdx.x] = d;
        __syncthreads();
#pragma unroll
        for (int st = TPB / 2; st > 0; st >>= 1){
            if (threadIdx.x < st) sh[threadIdx.x] += sh[threadIdx.x + st];
            __syncthreads();
        }
        if (threadIdx.x == 0){
            out[0] = (float)(sh[0] / ((double)OUTW * (double)OUTW));
            g_count = 0;   // reset for the next graph replay (deterministic)
        }
    }
}

extern "C" void kernel_launch(void* const* d_in, const int* in_sizes, int n_in,
                              void* d_out, int out_size) {
    (void)in_sizes; (void)n_in; (void)out_size;
    const float* O = (const float*)d_in[0];   // "output" image
    const float* T = (const float*)d_in[1];   // "target" image
    dim3 grid(NTX, NSTRIPS);
    ssim_main<<<grid, TPB>>>(O, T, (float*)d_out);
}

// round 16
// speedup vs baseline: 1.0107x; 1.0107x over previous
#include <cuda_runtime.h>

typedef unsigned long long u64;

// ---------------- problem constants ----------------
#define HW      4096
#define OUTW    4090          // valid output size (HW - 6)
#define TPB     128
#define KCOLS   8             // output columns per thread
#define RROWS   28            // output rows per block strip
#define NTX     4             // 4 * 128 * 8 = 4096 columns
#define NSTRIPS 148           // 148 * 28 = 4144 >= 4090 ; 4*148 = 592 blocks = 4/SM
#define NBLOCKS (NTX * NSTRIPS)

#define SSIM_C1 0.0004f            // (0.01*2)^2
#define SSIM_C2 0.0036f            // (0.03*2)^2
#define INV49   (1.0f/49.0f)
#define H1CONST (0.5f*INV49*INV49) // A1 = H1*(wP^2 - wM^2) + C1
#define G1CONST (1.0f/96.0f)       // A2 = G1*(a2 - b2) + C2  (covnorm/2/49 folded)

__device__ float g_partials[NBLOCKS];
__device__ int   g_count = 0;

// ---------------- packed f32x2 helpers (ptxas never emits FFMA2 from C++) ----
__device__ __forceinline__ u64 f2add(u64 a, u64 b){ u64 r; asm("add.rn.f32x2 %0,%1,%2;" : "=l"(r) : "l"(a), "l"(b)); return r; }
__device__ __forceinline__ u64 f2mul(u64 a, u64 b){ u64 r; asm("mul.rn.f32x2 %0,%1,%2;" : "=l"(r) : "l"(a), "l"(b)); return r; }
__device__ __forceinline__ u64 f2fma(u64 a, u64 b, u64 c){ u64 r; asm("fma.rn.f32x2 %0,%1,%2,%3;" : "=l"(r) : "l"(a), "l"(b), "l"(c)); return r; }
__device__ __forceinline__ u64 pack2(float lo, float hi){ u64 r; asm("mov.b64 %0,{%1,%2};" : "=l"(r) : "f"(lo), "f"(hi)); return r; }
__device__ __forceinline__ float2 unpack2(u64 v){ float2 r; asm("mov.b64 {%0,%1},%2;" : "=f"(r.x), "=f"(r.y) : "l"(v)); return r; }
__device__ __forceinline__ u64 bcast2(float f){ return pack2(f, f); }

// From 7 column-pair sums (14 scalar columns), build 4 packed pixel-pair
// 7-wide horizontal window sums: W[p] = { w(2p), w(2p+1) }.
__device__ __forceinline__ void windows(const u64* s, u64* W){
    float v[14];
#pragma unroll
    for (int j = 0; j < 7; ++j){ float2 t = unpack2(s[j]); v[2*j] = t.x; v[2*j+1] = t.y; }
    float w = v[0]+v[1]+v[2]+v[3]+v[4]+v[5]+v[6];
#pragma unroll
    for (int p = 0; p < 4; ++p){
        float w0 = w;
        w = w - v[2*p] + v[2*p+7];
        float w1 = w;
        if (p < 3) w = w - v[2*p+1] + v[2*p+8];
        W[p] = pack2(w0, w1);
    }
}

__global__ __launch_bounds__(TPB, 3)
void ssim_main(const float* __restrict__ O, const float* __restrict__ T,
               float* __restrict__ out) {
    const int base = blockIdx.x * (TPB * KCOLS) + threadIdx.x * KCOLS;
    const int y0   = blockIdx.y * RROWS;
    const int yend = min(y0 + RROWS, OUTW);
    const int nvalid = min(KCOLS, OUTW - base);   // >= 2 for every thread

    float acc = 0.f;

    if (y0 < yend) {
        // 7 column-pair offsets (u64 index), clamped for the single tail thread.
        // Clamped pairs only feed invalid output columns (nvalid guards them).
        int off2[7];
#pragma unroll
        for (int j = 0; j < 7; ++j) off2[j] = min(base + 2*j, HW - 2) >> 1;

        const u64 NEG1 = bcast2(-1.0f);
        const u64 NI49 = bcast2(-INV49);
        const u64 H1v  = bcast2(H1CONST);
        const u64 G1v  = bcast2(G1CONST);
        const u64 C1v  = bcast2(SSIM_C1);
        const u64 C2v  = bcast2(SSIM_C2);

        // Packed vertical column sums over 7 rows: P=O+T, M=O-T, P^2, M^2.
        u64 sP[7], sM[7], sPP[7], sMM[7];
#pragma unroll
        for (int j = 0; j < 7; ++j){ sP[j]=0; sM[j]=0; sPP[j]=0; sMM[j]=0; }

        // ---- init: rows y0 .. y0+6 ----
        for (int r = 0; r < 7; ++r){
            const u64* oR = reinterpret_cast<const u64*>(O + (y0 + r) * HW);
            const u64* tR = reinterpret_cast<const u64*>(T + (y0 + r) * HW);
#pragma unroll
            for (int j = 0; j < 7; ++j){
                u64 o = oR[off2[j]], t = tR[off2[j]];
                u64 P = f2add(o, t);
                u64 M = f2fma(t, NEG1, o);
                sP[j]  = f2add(sP[j], P);
                sM[j]  = f2add(sM[j], M);
                sPP[j] = f2fma(P, P, sPP[j]);
                sMM[j] = f2fma(M, M, sMM[j]);
            }
        }

        for (int y = y0; y < yend; ++y){
            // ---- horizontal windows (packed pixel pairs) ----
            u64 WP[4], WM[4], WPP[4], WMM[4];
            windows(sP,  WP);  windows(sM,  WM);
            windows(sPP, WPP); windows(sMM, WMM);

            // ---- packed SSIM epilogue, 2 pixels per f32x2 op ----
#pragma unroll
            for (int p = 0; p < 4; ++p){
                u64 PS2 = f2mul(WP[p], WP[p]);          // wP^2 (unscaled)
                u64 MS2 = f2mul(WM[p], WM[p]);
                u64 a2  = f2fma(PS2, NI49, WPP[p]);     // wPP - wP^2/49
                u64 b2  = f2fma(MS2, NI49, WMM[p]);
                u64 df1 = f2fma(MS2, NEG1, PS2);        // PS2 - MS2
                u64 sm1 = f2add(PS2, MS2);
                u64 A1  = f2fma(df1, H1v, C1v);         // 2*ux*uy + C1
                u64 B1  = f2fma(sm1, H1v, C1v);         // ux^2+uy^2 + C1
                u64 df2 = f2fma(b2, NEG1, a2);
                u64 sm2 = f2add(a2, b2);
                u64 A2  = f2fma(df2, G1v, C2v);         // 2*vxy + C2
                u64 B2  = f2fma(sm2, G1v, C2v);         // vx+vy + C2
                float2 num = unpack2(f2mul(A1, A2));
                float2 den = unpack2(f2mul(B1, B2));
                if (2*p     < nvalid) acc += __fdividef(num.x, den.x);
                if (2*p + 1 < nvalid) acc += __fdividef(num.y, den.y);
            }

            // ---- packed vertical slide: add row y+7, remove row y ----
            if (y + 1 < yend){
                const u64* oN = reinterpret_cast<const u64*>(O + (y + 7) * HW);
                const u64* tN = reinterpret_cast<const u64*>(T + (y + 7) * HW);
                const u64* oO = reinterpret_cast<const u64*>(O + y * HW);   // L1/L2-hot
                const u64* tO = reinterpret_cast<const u64*>(T + y * HW);
#pragma unroll
                for (int j = 0; j < 7; ++j){
                    u64 on = oN[off2[j]], tn = tN[off2[j]];
                    u64 oo = oO[off2[j]], to = tO[off2[j]];
                    u64 Pn = f2add(on, tn);
                    u64 Mn = f2fma(tn, NEG1, on);
                    u64 Po = f2add(oo, to);
                    u64 Mo = f2fma(to, NEG1, oo);
                    u64 dP = f2fma(Po, NEG1, Pn);
                    u64 dM = f2fma(Mo, NEG1, Mn);
                    sP[j] = f2add(sP[j], dP);
                    sM[j] = f2add(sM[j], dM);
                    u64 tP = f2add(Pn, Po);
                    u64 tM = f2add(Mn, Mo);
                    sPP[j] = f2fma(dP, tP, sPP[j]);     // Pn^2 - Po^2
                    sMM[j] = f2fma(dM, tM, sMM[j]);
                }
            }
        }
    }

    // ---- deterministic block reduction ----
#pragma unroll
    for (int o = 16; o > 0; o >>= 1)
        acc += __shfl_down_sync(0xffffffffu, acc, o);

    __shared__ float warpsum[TPB / 32];
    __shared__ bool  amLast;
    if ((threadIdx.x & 31) == 0) warpsum[threadIdx.x >> 5] = acc;
    __syncthreads();
    if (threadIdx.x == 0){
        float s = warpsum[0] + warpsum[1] + warpsum[2] + warpsum[3];
        g_partials[blockIdx.y * gridDim.x + blockIdx.x] = s;
        __threadfence();
        int prev = atomicAdd(&g_count, 1);
        amLast = (prev == NBLOCKS - 1);
    }
    __syncthreads();

    // ---- fused finalize: last block reduces all partials (fixed order) ----
    if (amLast){
        __shared__ double sh[TPB];
        double d = 0.0;
        for (int i = threadIdx.x; i < NBLOCKS; i += TPB)
            d += (double)g_partials[i];
        sh[threadIdx.x] = d;
        __syncthreads();
#pragma unroll
        for (int st = TPB / 2; st > 0; st >>= 1){
            if (threadIdx.x < st) sh[threadIdx.x] += sh[threadIdx.x + st];
            __syncthreads();
        }
        if (threadIdx.x == 0){
            out[0] = (float)(sh[0] / ((double)OUTW * (double)OUTW));
            g_count = 0;   // reset for the next graph replay (deterministic)
        }
    }
}

extern "C" void kernel_launch(void* const* d_in, const int* in_sizes, int n_in,
                              void* d_out, int out_size) {
    (void)in_sizes; (void)n_in; (void)out_size;
    const float* O = (const float*)d_in[0];   // "output" image
    const float* T = (const float*)d_in[1];   // "target" image
    dim3 grid(NTX, NSTRIPS);
    ssim_main<<<grid, TPB>>>(O, T, (float*)d_out);
}

// round 17
// speedup vs baseline: 1.0478x; 1.0368x over previous
#include <cuda_runtime.h>

typedef unsigned long long u64;

// ---------------- problem constants ----------------
#define HW      4096
#define OUTW    4090          // valid output size (HW - 6)
#define TPB     128
#define KCOLS   8             // output columns per thread
#define RROWS   28            // output rows per block strip
#define NTX     4             // 4 * 128 * 8 = 4096 columns
#define NSTRIPS 148           // 148 * 28 = 4144 >= 4090 ; 4*148 = 592 blocks = 4/SM
#define NBLOCKS (NTX * NSTRIPS)

#define SSIM_C1 0.0004f            // (0.01*2)^2
#define SSIM_C2 0.0036f            // (0.03*2)^2
#define INV49   (1.0f/49.0f)
#define H1CONST (0.5f*INV49*INV49) // A1 = H1*(wP^2 - wM^2) + C1
#define G1CONST (1.0f/96.0f)       // A2 = G1*(a2 - b2) + C2  (covnorm/2/49 folded)

__device__ float g_partials[NBLOCKS];
__device__ int   g_count = 0;

// ---------------- packed f32x2 helpers (ptxas never emits FFMA2 from C++) ----
__device__ __forceinline__ u64 f2add(u64 a, u64 b){ u64 r; asm("add.rn.f32x2 %0,%1,%2;" : "=l"(r) : "l"(a), "l"(b)); return r; }
__device__ __forceinline__ u64 f2mul(u64 a, u64 b){ u64 r; asm("mul.rn.f32x2 %0,%1,%2;" : "=l"(r) : "l"(a), "l"(b)); return r; }
__device__ __forceinline__ u64 f2fma(u64 a, u64 b, u64 c){ u64 r; asm("fma.rn.f32x2 %0,%1,%2,%3;" : "=l"(r) : "l"(a), "l"(b), "l"(c)); return r; }
__device__ __forceinline__ u64 pack2(float lo, float hi){ u64 r; asm("mov.b64 %0,{%1,%2};" : "=l"(r) : "f"(lo), "f"(hi)); return r; }
__device__ __forceinline__ float2 unpack2(u64 v){ float2 r; asm("mov.b64 {%0,%1},%2;" : "=f"(r.x), "=f"(r.y) : "l"(v)); return r; }
__device__ __forceinline__ u64 bcast2(float f){ return pack2(f, f); }

// From 7 column-pair sums (14 scalar columns), build 4 packed pixel-pair
// 7-wide horizontal window sums: W[p] = { w(2p), w(2p+1) }.
__device__ __forceinline__ void windows(const u64* s, u64* W){
    float v[14];
#pragma unroll
    for (int j = 0; j < 7; ++j){ float2 t = unpack2(s[j]); v[2*j] = t.x; v[2*j+1] = t.y; }
    float w = v[0]+v[1]+v[2]+v[3]+v[4]+v[5]+v[6];
#pragma unroll
    for (int p = 0; p < 4; ++p){
        float w0 = w;
        w = w - v[2*p] + v[2*p+7];
        float w1 = w;
        if (p < 3) w = w - v[2*p+1] + v[2*p+8];
        W[p] = pack2(w0, w1);
    }
}

__global__ __launch_bounds__(TPB, 3)
void ssim_main(const float* __restrict__ O, const float* __restrict__ T,
               float* __restrict__ out) {
    const int base = blockIdx.x * (TPB * KCOLS) + threadIdx.x * KCOLS;
    const int y0   = blockIdx.y * RROWS;
    const int yend = min(y0 + RROWS, OUTW);
    const int nvalid = min(KCOLS, OUTW - base);   // >= 2 for every thread

    float acc = 0.f;

    if (y0 < yend) {
        // 7 column-pair offsets (u64 index), clamped for the single tail thread.
        // Clamped pairs only feed invalid output columns (nvalid guards them).
        int off2[7];
#pragma unroll
        for (int j = 0; j < 7; ++j) off2[j] = min(base + 2*j, HW - 2) >> 1;

        const u64 NEG1 = bcast2(-1.0f);
        const u64 NI49 = bcast2(-INV49);
        const u64 H1v  = bcast2(H1CONST);
        const u64 G1v  = bcast2(G1CONST);
        const u64 C1v  = bcast2(SSIM_C1);
        const u64 C2v  = bcast2(SSIM_C2);

        // Packed vertical column sums over 7 rows: P=O+T, M=O-T, P^2, M^2.
        u64 sP[7], sM[7], sPP[7], sMM[7];
#pragma unroll
        for (int j = 0; j < 7; ++j){ sP[j]=0; sM[j]=0; sPP[j]=0; sMM[j]=0; }

        // ---- init: rows y0 .. y0+6 ----
        for (int r = 0; r < 7; ++r){
            const u64* oR = reinterpret_cast<const u64*>(O + (y0 + r) * HW);
            const u64* tR = reinterpret_cast<const u64*>(T + (y0 + r) * HW);
#pragma unroll
            for (int j = 0; j < 7; ++j){
                u64 o = oR[off2[j]], t = tR[off2[j]];
                u64 P = f2add(o, t);
                u64 M = f2fma(t, NEG1, o);
                sP[j]  = f2add(sP[j], P);
                sM[j]  = f2add(sM[j], M);
                sPP[j] = f2fma(P, P, sPP[j]);
                sMM[j] = f2fma(M, M, sMM[j]);
            }
        }

        for (int y = y0; y < yend; ++y){
            // ---- horizontal windows (packed pixel pairs) ----
            u64 WP[4], WM[4], WPP[4], WMM[4];
            windows(sP,  WP);  windows(sM,  WM);
            windows(sPP, WPP); windows(sMM, WMM);

            // ---- packed SSIM epilogue, 2 pixels per f32x2 op ----
#pragma unroll
            for (int p = 0; p < 4; ++p){
                u64 PS2 = f2mul(WP[p], WP[p]);          // wP^2 (unscaled)
                u64 MS2 = f2mul(WM[p], WM[p]);
                u64 a2  = f2fma(PS2, NI49, WPP[p]);     // wPP - wP^2/49
                u64 b2  = f2fma(MS2, NI49, WMM[p]);
                u64 df1 = f2fma(MS2, NEG1, PS2);        // PS2 - MS2
                u64 sm1 = f2add(PS2, MS2);
                u64 A1  = f2fma(df1, H1v, C1v);         // 2*ux*uy + C1
                u64 B1  = f2fma(sm1, H1v, C1v);         // ux^2+uy^2 + C1
                u64 df2 = f2fma(b2, NEG1, a2);
                u64 sm2 = f2add(a2, b2);
                u64 A2  = f2fma(df2, G1v, C2v);         // 2*vxy + C2
                u64 B2  = f2fma(sm2, G1v, C2v);         // vx+vy + C2
                float2 num = unpack2(f2mul(A1, A2));
                float2 den = unpack2(f2mul(B1, B2));
                if (2*p     < nvalid) acc += __fdividef(num.x, den.x);
                if (2*p + 1 < nvalid) acc += __fdividef(num.y, den.y);
            }

            // ---- packed vertical slide: add row y+7, remove row y ----
            if (y + 1 < yend){
                const u64* oN = reinterpret_cast<const u64*>(O + (y + 7) * HW);
                const u64* tN = reinterpret_cast<const u64*>(T + (y + 7) * HW);
                const u64* oO = reinterpret_cast<const u64*>(O + y * HW);   // L1/L2-hot
                const u64* tO = reinterpret_cast<const u64*>(T + y * HW);
#pragma unroll
                for (int j = 0; j < 7; ++j){
                    u64 on = oN[off2[j]], tn = tN[off2[j]];
                    u64 oo = oO[off2[j]], to = tO[off2[j]];
                    u64 Pn = f2add(on, tn);
                    u64 Mn = f2fma(tn, NEG1, on);
                    u64 Po = f2add(oo, to);
                    u64 Mo = f2fma(to, NEG1, oo);
                    u64 dP = f2fma(Po, NEG1, Pn);
                    u64 dM = f2fma(Mo, NEG1, Mn);
                    sP[j] = f2add(sP[j], dP);
                    sM[j] = f2add(sM[j], dM);
                    u64 tP = f2add(Pn, Po);
                    u64 tM = f2add(Mn, Mo);
                    sPP[j] = f2fma(dP, tP, sPP[j]);     // Pn^2 - Po^2
                    sMM[j] = f2fma(dM, tM, sMM[j]);
                }
            }
        }
    }

    // ---- deterministic block reduction ----
#pragma unroll
    for (int o = 16; o > 0; o >>= 1)
        acc += __shfl_down_sync(0xffffffffu, acc, o);

    __shared__ float warpsum[TPB / 32];
    __shared__ bool  amLast;
    if ((threadIdx.x & 31) == 0) warpsum[threadIdx.x >> 5] = acc;
    __syncthreads();
    if (threadIdx.x == 0){
        float s = warpsum[0] + warpsum[1] + warpsum[2] + warpsum[3];
        g_partials[blockIdx.y * gridDim.x + blockIdx.x] = s;
        __threadfence();
        int prev = atomicAdd(&g_count, 1);
        amLast = (prev == NBLOCKS - 1);
    }
    __syncthreads();

    // ---- fused finalize: last block reduces all partials (fixed order) ----
    if (amLast){
        __shared__ double sh[TPB];
        double d = 0.0;
        for (int i = threadIdx.x; i < NBLOCKS; i += TPB)
            d += (double)g_partials[i];
        sh[threadIdx.x] = d;
        __syncthreads();
#pragma unroll
        for (int st = TPB / 2; st > 0; st >>= 1){
            if (threadIdx.x < st) sh[threadIdx.x] += sh[threadIdx.x + st];
            __syncthreads();
        }
        if (threadIdx.x == 0){
            out[0] = (float)(sh[0] / ((double)OUTW * (double)OUTW));
            g_count = 0;   // reset for the next graph replay (deterministic)
        }
    }
}

extern "C" void kernel_launch(void* const* d_in, const int* in_sizes, int n_in,
                              void* d_out, int out_size) {
    (void)in_sizes; (void)n_in; (void)out_size;
    const float* O = (const float*)d_in[0];   // "output" image
    const float* T = (const float*)d_in[1];   // "target" image
    dim3 grid(NTX, NSTRIPS);
    ssim_main<<<grid, TPB>>>(O, T, (float*)d_out);
}